// round 14
// baseline (speedup 1.0000x reference)
#include <cuda_runtime.h>
#include <cuda_bf16.h>
#include <math.h>
#include <stdint.h>

#define LSEQ 1026
#define BB   2
#define BLT  (BB*LSEQ)   // 2052
#define DMO  256
#define EDI  512
#define ED2  1024
#define NS   16
#define RRW  16
#define DBCW 48
#define NBR  4
#define NCHK 27
#define CLEN 38          // 27*38 = 1026
#define EQ   128
#define TSTR 17          // uint2 per tile row (17*8=136B)

// ------------------------- scratch -------------------------------------------
__device__ float g_xz[(size_t)BLT*ED2];
__device__ float g_xa[NBR][(size_t)BLT*EDI];
__device__ float g_dbc[NBR][(size_t)BLT*DBCW];
__device__ float g_sum[(size_t)NBR*BB*NCHK*32*EDI];
__device__ float g_h0[(size_t)NBR*BB*NCHK*NS*EDI];
__device__ float g_g[NBR][(size_t)BLT*EDI];
__device__ float g_y[(size_t)BLT*EDI];

struct BranchPtrs { const float *cw,*cb,*xpw,*dtw,*dtb,*Al,*Dp; };
struct AllPtrs { BranchPtrs br[NBR]; };

// ------------------------- index maps -----------------------------------------
__device__ __forceinline__ int pi_map(int p) {
    if (p == 0 || p == LSEQ - 1) return p;
    int q = p - 1;
    int i = q >> 5, j = q & 31;
    return (j << 5) + i + 1;
}
__device__ __forceinline__ int in_row(int s, int p) {
    if (s == 0) return p;
    if (s == 1) return LSEQ - 1 - p;
    if (s == 2) return pi_map(p);
    return pi_map(LSEQ - 1 - p);
}

// ------------------------- bf16x2 split helpers --------------------------------
__device__ __forceinline__ void split_pair(float x0, float x1, uint32_t& hp, uint32_t& lp) {
    __nv_bfloat16 h0 = __float2bfloat16_rn(x0);
    __nv_bfloat16 h1 = __float2bfloat16_rn(x1);
    float r0 = x0 - __bfloat162float(h0);
    float r1 = x1 - __bfloat162float(h1);
    __nv_bfloat16 l0 = __float2bfloat16_rn(r0);
    __nv_bfloat16 l1 = __float2bfloat16_rn(r1);
    hp = ((uint32_t)__bfloat16_as_ushort(h1) << 16) | (uint32_t)__bfloat16_as_ushort(h0);
    lp = ((uint32_t)__bfloat16_as_ushort(l1) << 16) | (uint32_t)__bfloat16_as_ushort(l0);
}
__device__ __forceinline__ void mma_bf16(float c[4], const uint32_t a[4],
                                         uint32_t b0, uint32_t b1) {
    asm volatile("mma.sync.aligned.m16n8k16.row.col.f32.bf16.bf16.f32 "
        "{%0,%1,%2,%3}, {%4,%5,%6,%7}, {%8,%9}, {%0,%1,%2,%3};"
        : "+f"(c[0]), "+f"(c[1]), "+f"(c[2]), "+f"(c[3])
        : "r"(a[0]), "r"(a[1]), "r"(a[2]), "r"(a[3]), "r"(b0), "r"(b1));
}
__device__ __forceinline__ int swz(int row, int p) { return p ^ ((row & 7) << 1); }
__device__ __forceinline__ void store8(uint2* T, int row, int ka, float4 v0, float4 v1) {
    float v[8] = {v0.x, v0.y, v0.z, v0.w, v1.x, v1.y, v1.z, v1.w};
#pragma unroll
    for (int j = 0; j < 4; j++) {
        uint32_t hp, lp;
        split_pair(v[2*j], v[2*j+1], hp, lp);
        int p = (ka >> 1) + j;
        T[row * TSTR + swz(row, p)] = make_uint2(hp, lp);
    }
}
__device__ __forceinline__ void lda_frag(const uint2* T, int r0, int kk, int t4,
                                         uint32_t ah[4], uint32_t al[4]) {
    uint2 q0 = T[r0 * TSTR + swz(r0, kk*8 + t4)];
    uint2 q1 = T[(r0+8) * TSTR + swz(r0+8, kk*8 + t4)];
    uint2 q2 = T[r0 * TSTR + swz(r0, kk*8 + t4 + 4)];
    uint2 q3 = T[(r0+8) * TSTR + swz(r0+8, kk*8 + t4 + 4)];
    ah[0]=q0.x; ah[1]=q1.x; ah[2]=q2.x; ah[3]=q3.x;
    al[0]=q0.y; al[1]=q1.y; al[2]=q2.y; al[3]=q3.y;
}
__device__ __forceinline__ void mma3(const uint2* Bt, int n, int kk, int t4,
                                     const uint32_t ah[4], const uint32_t al[4],
                                     float acc[4]) {
    uint2 p0 = Bt[n * TSTR + swz(n, kk*8 + t4)];
    uint2 p1 = Bt[n * TSTR + swz(n, kk*8 + t4 + 4)];
    mma_bf16(acc, ah, p0.y, p1.y);
    mma_bf16(acc, al, p0.x, p1.x);
    mma_bf16(acc, ah, p0.x, p1.x);
}

// ====== in-GEMM (bf16x3): xz = x @ in_w^T. 128x64 tile, K=256, 272 blocks ===
__global__ __launch_bounds__(256)
void in_gemm_mma(const float* __restrict__ A, const float* __restrict__ Bm,
                 float* __restrict__ C) {
    __shared__ uint2 At[128 * TSTR];
    __shared__ uint2 Bt[64 * TSTR];
    int tid = threadIdx.x;
    int n0 = blockIdx.x * 64, m0 = blockIdx.y * 128;
    int ra = tid >> 1, ka = (tid & 1) * 16;
    bool mok = (m0 + ra) < BLT;
    const float* Ap = A + (size_t)(m0 + ra) * DMO + ka;
    int rb = tid >> 2, kb = (tid & 3) * 8;
    const float* Bp = Bm + (size_t)(n0 + rb) * DMO + kb;
    int lane = tid & 31, wid = tid >> 5;
    int g = lane >> 2, t4 = lane & 3;
    int wm = (wid & 3) * 32, wn = (wid >> 2) * 32;

    float4 a[4], b[2];
#pragma unroll
    for (int i = 0; i < 4; i++)
        a[i] = mok ? *(const float4*)(Ap + 4*i) : make_float4(0,0,0,0);
    b[0] = *(const float4*)Bp; b[1] = *(const float4*)(Bp + 4);

    float acc[2][4][4];
#pragma unroll
    for (int mi = 0; mi < 2; mi++)
#pragma unroll
        for (int ni = 0; ni < 4; ni++)
#pragma unroll
            for (int q = 0; q < 4; q++) acc[mi][ni][q] = 0.f;

#pragma unroll 1
    for (int s = 0; s < 8; s++) {
        store8(At, ra, ka, a[0], a[1]);
        store8(At, ra, ka + 8, a[2], a[3]);
        store8(Bt, rb, kb, b[0], b[1]);
        __syncthreads();
        if (s + 1 < 8) {
            int off = 32 * (s + 1);
#pragma unroll
            for (int i = 0; i < 4; i++)
                a[i] = mok ? *(const float4*)(Ap + off + 4*i) : make_float4(0,0,0,0);
            b[0] = *(const float4*)(Bp + off); b[1] = *(const float4*)(Bp + off + 4);
        }
#pragma unroll
        for (int kk = 0; kk < 2; kk++) {
            uint32_t ah[2][4], al[2][4];
            lda_frag(At, wm + g, kk, t4, ah[0], al[0]);
            lda_frag(At, wm + 16 + g, kk, t4, ah[1], al[1]);
#pragma unroll
            for (int ni = 0; ni < 4; ni++) {
                int n = wn + ni * 8 + g;
                uint2 p0 = Bt[n * TSTR + swz(n, kk*8 + t4)];
                uint2 p1 = Bt[n * TSTR + swz(n, kk*8 + t4 + 4)];
#pragma unroll
                for (int mi = 0; mi < 2; mi++) {
                    mma_bf16(acc[mi][ni], ah[mi], p0.y, p1.y);
                    mma_bf16(acc[mi][ni], al[mi], p0.x, p1.x);
                    mma_bf16(acc[mi][ni], ah[mi], p0.x, p1.x);
                }
            }
        }
        __syncthreads();
    }
#pragma unroll
    for (int mi = 0; mi < 2; mi++)
#pragma unroll
        for (int ni = 0; ni < 4; ni++) {
            int row = m0 + wm + mi * 16 + g;
            int col = n0 + wn + ni * 8 + 2 * t4;
            if (row < BLT)
                *(float2*)&C[(size_t)row * ED2 + col] =
                    make_float2(acc[mi][ni][0], acc[mi][ni][1]);
            if (row + 8 < BLT)
                *(float2*)&C[(size_t)(row + 8) * ED2 + col] =
                    make_float2(acc[mi][ni][2], acc[mi][ni][3]);
        }
}

// ====== dBC (bf16x3): 64x48, split-K(4), 256 thr, atomic ====================
__global__ __launch_bounds__(256)
void dbc_mma(AllPtrs P) {
    __shared__ uint2 At[64 * TSTR];
    __shared__ uint2 Bt[48 * TSTR];
    int tid = threadIdx.x;
    int s = blockIdx.x;
    int m0 = blockIdx.y * 64;
    int kbase = blockIdx.z * 128;
    const float* A  = g_xa[s];
    const float* Bm = P.br[s].xpw;
    float*       C  = g_dbc[s];
    int ra = tid >> 2, ka = (tid & 3) * 8;
    bool mok = (m0 + ra) < BLT;
    const float* Ap = A + (size_t)(m0 + ra) * EDI + kbase + ka;
    bool bok = tid < 192;
    int rb = tid >> 2;
    const float* Bp = Bm + (size_t)rb * EDI + kbase + ka;
    int lane = tid & 31, wid = tid >> 5;
    int g = lane >> 2, t4 = lane & 3;
    int wm = (wid & 3) * 16, wn = (wid >> 2) * 24;

    float4 a[2], b[2];
    a[0] = mok ? *(const float4*)Ap : make_float4(0,0,0,0);
    a[1] = mok ? *(const float4*)(Ap + 4) : make_float4(0,0,0,0);
    b[0] = bok ? *(const float4*)Bp : make_float4(0,0,0,0);
    b[1] = bok ? *(const float4*)(Bp + 4) : make_float4(0,0,0,0);

    float acc[3][4];
#pragma unroll
    for (int ni = 0; ni < 3; ni++)
#pragma unroll
        for (int q = 0; q < 4; q++) acc[ni][q] = 0.f;

#pragma unroll 1
    for (int s2 = 0; s2 < 4; s2++) {
        store8(At, ra, ka, a[0], a[1]);
        if (bok) store8(Bt, rb, ka, b[0], b[1]);
        __syncthreads();
        if (s2 + 1 < 4) {
            int off = 32 * (s2 + 1);
            a[0] = mok ? *(const float4*)(Ap + off) : make_float4(0,0,0,0);
            a[1] = mok ? *(const float4*)(Ap + off + 4) : make_float4(0,0,0,0);
            b[0] = bok ? *(const float4*)(Bp + off) : make_float4(0,0,0,0);
            b[1] = bok ? *(const float4*)(Bp + off + 4) : make_float4(0,0,0,0);
        }
#pragma unroll
        for (int kk = 0; kk < 2; kk++) {
            uint32_t ah[4], al[4];
            lda_frag(At, wm + g, kk, t4, ah, al);
#pragma unroll
            for (int ni = 0; ni < 3; ni++)
                mma3(Bt, wn + ni * 8 + g, kk, t4, ah, al, acc[ni]);
        }
        __syncthreads();
    }
#pragma unroll
    for (int ni = 0; ni < 3; ni++) {
        int row = m0 + wm + g;
        int col = wn + ni * 8 + 2 * t4;
        if (row < BLT) {
            atomicAdd(&C[(size_t)row * DBCW + col], acc[ni][0]);
            atomicAdd(&C[(size_t)row * DBCW + col + 1], acc[ni][1]);
        }
        if (row + 8 < BLT) {
            atomicAdd(&C[(size_t)(row + 8) * DBCW + col], acc[ni][2]);
            atomicAdd(&C[(size_t)(row + 8) * DBCW + col + 1], acc[ni][3]);
        }
    }
}

// ====== out-GEMM (bf16x3): y @ out_w^T. 64x64, split-K(2), atomic ===========
__global__ __launch_bounds__(256)
void out_gemm_mma(const float* __restrict__ out_w, float* __restrict__ C) {
    __shared__ uint2 At[64 * TSTR];
    __shared__ uint2 Bt[64 * TSTR];
    int tid = threadIdx.x;
    int n0 = blockIdx.x * 64, m0 = blockIdx.y * 64;
    int kbase = blockIdx.z * 256;
    int ra = tid >> 2, ka = (tid & 3) * 8;
    bool mok = (m0 + ra) < BLT;
    const float* Ap = g_y + (size_t)(m0 + ra) * EDI + kbase + ka;
    const float* Bp = out_w + (size_t)(n0 + ra) * EDI + kbase + ka;
    int lane = tid & 31, wid = tid >> 5;
    int g = lane >> 2, t4 = lane & 3;
    int wm = (wid & 3) * 16, wn = (wid >> 2) * 32;

    float4 a[2], b[2];
    a[0] = mok ? *(const float4*)Ap : make_float4(0,0,0,0);
    a[1] = mok ? *(const float4*)(Ap + 4) : make_float4(0,0,0,0);
    b[0] = *(const float4*)Bp; b[1] = *(const float4*)(Bp + 4);

    float acc[4][4];
#pragma unroll
    for (int ni = 0; ni < 4; ni++)
#pragma unroll
        for (int q = 0; q < 4; q++) acc[ni][q] = 0.f;

#pragma unroll 1
    for (int s2 = 0; s2 < 8; s2++) {
        store8(At, ra, ka, a[0], a[1]);
        store8(Bt, ra, ka, b[0], b[1]);
        __syncthreads();
        if (s2 + 1 < 8) {
            int off = 32 * (s2 + 1);
            a[0] = mok ? *(const float4*)(Ap + off) : make_float4(0,0,0,0);
            a[1] = mok ? *(const float4*)(Ap + off + 4) : make_float4(0,0,0,0);
            b[0] = *(const float4*)(Bp + off); b[1] = *(const float4*)(Bp + off + 4);
        }
#pragma unroll
        for (int kk = 0; kk < 2; kk++) {
            uint32_t ah[4], al[4];
            lda_frag(At, wm + g, kk, t4, ah, al);
#pragma unroll
            for (int ni = 0; ni < 4; ni++)
                mma3(Bt, wn + ni * 8 + g, kk, t4, ah, al, acc[ni]);
        }
        __syncthreads();
    }
#pragma unroll
    for (int ni = 0; ni < 4; ni++) {
        int row = m0 + wm + g;
        int col = n0 + wn + ni * 8 + 2 * t4;
        if (row < BLT) {
            atomicAdd(&C[(size_t)row * DMO + col], acc[ni][0]);
            atomicAdd(&C[(size_t)row * DMO + col + 1], acc[ni][1]);
        }
        if (row + 8 < BLT) {
            atomicAdd(&C[(size_t)(row + 8) * DMO + col], acc[ni][2]);
            atomicAdd(&C[(size_t)(row + 8) * DMO + col + 1], acc[ni][3]);
        }
    }
}

// ---------- combine: y = 0.25*(g0 + rev(g1) + cross(g2) + revcross(g3)) -----
__global__ __launch_bounds__(128)
void combine_k() {
    int bl = blockIdx.x;
    int b = bl / LSEQ, l = bl % LSEQ;
    int e4 = threadIdx.x * 4;
    size_t r0 = (size_t)bl * EDI + e4;
    size_t r1 = (size_t)(b * LSEQ + (LSEQ - 1 - l)) * EDI + e4;
    size_t r2 = (size_t)(b * LSEQ + pi_map(l)) * EDI + e4;
    size_t r3 = (size_t)(b * LSEQ + pi_map(LSEQ - 1 - l)) * EDI + e4;
    float4 p0 = *(const float4*)(g_g[0] + r0);
    float4 p1 = *(const float4*)(g_g[1] + r1);
    float4 p2 = *(const float4*)(g_g[2] + r2);
    float4 p3 = *(const float4*)(g_g[3] + r3);
    float4 o;
    o.x = 0.25f * (p0.x + p1.x + p2.x + p3.x);
    o.y = 0.25f * (p0.y + p1.y + p2.y + p3.y);
    o.z = 0.25f * (p0.z + p1.z + p2.z + p3.z);
    o.w = 0.25f * (p0.w + p1.w + p2.w + p3.w);
    *(float4*)(g_y + r0) = o;
}

// ------- depthwise conv (K=4 causal) + SiLU ---------------------------------
#define CONV_T 6
__global__ __launch_bounds__(512)
void conv_silu(AllPtrs P) {
    int blk = blockIdx.x;
    int ntile = LSEQ / CONV_T;
    int s  = blk / (BB * ntile);
    int rm = blk % (BB * ntile);
    int b  = rm / ntile;
    int l0 = (rm % ntile) * CONV_T;
    int e  = threadIdx.x;
    float4 cwv = *(const float4*)(P.br[s].cw + e * 4);
    float cb = P.br[s].cb[e];
    float v0 = 0.f, v1 = 0.f, v2 = 0.f;
    if (l0 - 3 >= 0) v0 = g_xz[(size_t)(b * LSEQ + in_row(s, l0 - 3)) * ED2 + e];
    if (l0 - 2 >= 0) v1 = g_xz[(size_t)(b * LSEQ + in_row(s, l0 - 2)) * ED2 + e];
    if (l0 - 1 >= 0) v2 = g_xz[(size_t)(b * LSEQ + in_row(s, l0 - 1)) * ED2 + e];
#pragma unroll
    for (int t = 0; t < CONV_T; t++) {
        int l = l0 + t;
        float v3 = g_xz[(size_t)(b * LSEQ + in_row(s, l)) * ED2 + e];
        float acc = cb;
        acc = fmaf(cwv.x, v0, acc);
        acc = fmaf(cwv.y, v1, acc);
        acc = fmaf(cwv.z, v2, acc);
        acc = fmaf(cwv.w, v3, acc);
        float sg = 1.f / (1.f + __expf(-acc));
        g_xa[s][(size_t)(b * LSEQ + l) * EDI + e] = acc * sg;
        v0 = v1; v1 = v2; v2 = v3;
    }
}

// -------- scan phase 1: chunk summaries, delta fused, channel-quarter -------
__global__ __launch_bounds__(128)
void scan1(AllPtrs P) {
    __shared__ float dtw_s[EQ * 17];
    __shared__ float f_s[CLEN][NS];
    __shared__ float Bsm[CLEN * NS];
    int blk = blockIdx.x;
    int quarter = blk & 3;
    int blk2 = blk >> 2;
    int s = blk2 / (BB * NCHK);
    int rem = blk2 % (BB * NCHK);
    int b = rem / NCHK, c = rem % NCHK;
    int e0 = quarter * EQ;
    int e = e0 + threadIdx.x;
    const float* dtw = P.br[s].dtw;
    for (int idx = threadIdx.x; idx < EQ * RRW; idx += blockDim.x)
        dtw_s[(idx >> 4) * 17 + (idx & 15)] = dtw[e0 * RRW + idx];
    for (int idx = threadIdx.x; idx < CLEN * 32; idx += blockDim.x) {
        int t = idx >> 5, q = idx & 31;
        float v = g_dbc[s][(size_t)(b * LSEQ + c * CLEN + t) * DBCW + q];
        if (q < 16) f_s[t][q] = v;
        else        Bsm[t * NS + (q - 16)] = v;
    }
    __syncthreads();
    float w[RRW];
#pragma unroll
    for (int q = 0; q < RRW; q++) w[q] = dtw_s[threadIdx.x * 17 + q];
    float dtb = P.br[s].dtb[e];
    const float* Al = P.br[s].Al;
    float A_[NS];
    bool fastb = true;
#pragma unroll
    for (int n = 0; n < NS; n++) {
        float av = -__expf(Al[e * NS + n]);
        A_[n] = av;
        if (fabsf(av + (float)(n + 1)) > 1e-4f * (float)(n + 1)) fastb = false;
    }
    float h[NS], Pn[NS];
#pragma unroll
    for (int n = 0; n < NS; n++) { h[n] = 0.f; Pn[n] = 1.f; }
    float Rp = 1.f;
    const float* xptr = g_xa[s] + (size_t)(b * LSEQ + c * CLEN) * EDI + e;
    float x_cur = *xptr;
    const float* xn = xptr + EDI;
    for (int t = 0; t < CLEN; t++) {
        float x_nxt = (t + 1 < CLEN) ? *xn : 0.f;
        xn += EDI;
        float u = dtb;
#pragma unroll
        for (int q = 0; q < RRW; q++) u = fmaf(f_s[t][q], w[q], u);
        float d = fmaxf(u, 0.f) + log1pf(__expf(-fabsf(u)));
        float dx = d * x_cur;
        if (fastb) {
            float r = __expf(-d);
            Rp *= r;
            float dA = 1.f;
#pragma unroll
            for (int n = 0; n < NS; n++) {
                dA *= r;
                h[n] = fmaf(dA, h[n], dx * Bsm[t * NS + n]);
            }
        } else {
#pragma unroll
            for (int n = 0; n < NS; n++) {
                float dA = __expf(d * A_[n]);
                Pn[n] *= dA;
                h[n] = fmaf(dA, h[n], dx * Bsm[t * NS + n]);
            }
        }
        x_cur = x_nxt;
    }
    if (fastb) {
        float q = 1.f;
#pragma unroll
        for (int n = 0; n < NS; n++) { q *= Rp; Pn[n] = q; }
    }
    size_t base = (size_t)((s * BB + b) * NCHK + c) * 32 * EDI + e;
#pragma unroll
    for (int n = 0; n < NS; n++) g_sum[base + (size_t)n * EDI] = h[n];
#pragma unroll
    for (int n = 0; n < NS; n++) g_sum[base + (size_t)(16 + n) * EDI] = Pn[n];
}

// ---------- scan phase 2: chunk combine, all loads prefetched ---------------
__global__ __launch_bounds__(512)
void scan2() {
    int n = blockIdx.x & 15;
    int sb = blockIdx.x >> 4;
    int e = threadIdx.x;
    float hl[NCHK], Pv[NCHK];
#pragma unroll
    for (int c = 0; c < NCHK; c++) {
        size_t pb = (size_t)(sb * NCHK + c) * 32 * EDI + e;
        hl[c] = g_sum[pb + (size_t)n * EDI];
        Pv[c] = g_sum[pb + (size_t)(16 + n) * EDI];
    }
    float h = 0.f;
#pragma unroll
    for (int c = 0; c < NCHK; c++) {
        g_h0[(size_t)(sb * NCHK + c) * NS * EDI + (size_t)n * EDI + e] = h;
        h = fmaf(Pv[c], h, hl[c]);
    }
}

// -------- scan phase 3: full walk + gate, delta fused, channel-quarter ------
__global__ __launch_bounds__(128)
void scan3(AllPtrs P) {
    __shared__ float dtw_s[EQ * 17];
    __shared__ float f_s[CLEN][NS];
    __shared__ float Bsm[CLEN * NS];
    __shared__ float Csm[CLEN * NS];
    int blk = blockIdx.x;
    int quarter = blk & 3;
    int blk2 = blk >> 2;
    int s = blk2 / (BB * NCHK);
    int rem = blk2 % (BB * NCHK);
    int b = rem / NCHK, c = rem % NCHK;
    int e0 = quarter * EQ;
    int e = e0 + threadIdx.x;
    const float* dtw = P.br[s].dtw;
    for (int idx = threadIdx.x; idx < EQ * RRW; idx += blockDim.x)
        dtw_s[(idx >> 4) * 17 + (idx & 15)] = dtw[e0 * RRW + idx];
    for (int idx = threadIdx.x; idx < CLEN * DBCW; idx += blockDim.x) {
        int t = idx / DBCW, q = idx % DBCW;
        float v = g_dbc[s][(size_t)(b * LSEQ + c * CLEN + t) * DBCW + q];
        if (q < 16)      f_s[t][q] = v;
        else if (q < 32) Bsm[t * NS + (q - 16)] = v;
        else             Csm[t * NS + (q - 32)] = v;
    }
    __syncthreads();
    float w[RRW];
#pragma unroll
    for (int q = 0; q < RRW; q++) w[q] = dtw_s[threadIdx.x * 17 + q];
    float dtb = P.br[s].dtb[e];
    const float* Al = P.br[s].Al;
    float A_[NS];
    bool fastb = true;
#pragma unroll
    for (int n = 0; n < NS; n++) {
        float av = -__expf(Al[e * NS + n]);
        A_[n] = av;
        if (fabsf(av + (float)(n + 1)) > 1e-4f * (float)(n + 1)) fastb = false;
    }
    float Dv = P.br[s].Dp[e];
    float h[NS];
    {
        size_t sb = (size_t)((s * BB + b) * NCHK + c);
        size_t hb = sb * NS * EDI + e;
#pragma unroll
        for (int n = 0; n < NS; n++) h[n] = g_h0[hb + (size_t)n * EDI];
    }
    int l0 = c * CLEN;
    size_t bbase = (size_t)(b * LSEQ);
    const float* xptr = g_xa[s] + (size_t)(bbase + l0) * EDI + e;
    float* gout = g_g[s] + (size_t)(bbase + l0) * EDI + e;
    float x_cur = *xptr;
    const float* xn = xptr + EDI;
    float za_cur = g_xz[(bbase + in_row(s, l0)) * ED2 + EDI + e];
    for (int t = 0; t < CLEN; t++) {
        float x_nxt = 0.f, za_nxt = 0.f;
        if (t + 1 < CLEN) {
            x_nxt = *xn;
            za_nxt = g_xz[(bbase + in_row(s, l0 + t + 1)) * ED2 + EDI + e];
        }
        xn += EDI;
        float u = dtb;
#pragma unroll
        for (int q = 0; q < RRW; q++) u = fmaf(f_s[t][q], w[q], u);
        float d = fmaxf(u, 0.f) + log1pf(__expf(-fabsf(u)));
        float dx = d * x_cur;
        float acc = Dv * x_cur;
        if (fastb) {
            float r = __expf(-d);
            float dA = 1.f;
#pragma unroll
            for (int n = 0; n < NS; n++) {
                dA *= r;
                h[n] = fmaf(dA, h[n], dx * Bsm[t * NS + n]);
                acc = fmaf(h[n], Csm[t * NS + n], acc);
            }
        } else {
#pragma unroll
            for (int n = 0; n < NS; n++) {
                float dA = __expf(d * A_[n]);
                h[n] = fmaf(dA, h[n], dx * Bsm[t * NS + n]);
                acc = fmaf(h[n], Csm[t * NS + n], acc);
            }
        }
        float sz = za_cur / (1.f + __expf(-za_cur));
        *gout = acc * sz;
        gout += EDI;
        x_cur = x_nxt; za_cur = za_nxt;
    }
}

// ------------------------- launch ------------------------------------------
extern "C" void kernel_launch(void* const* d_in, const int* in_sizes, int n_in,
                              void* d_out, int out_size) {
    const float* x     = (const float*)d_in[0];
    const float* in_w  = (const float*)d_in[1];
    const float* out_w = (const float*)d_in[2];
    AllPtrs P;
    for (int s = 0; s < NBR; s++) {
        int o = 3 + 7 * s;
        P.br[s].cw  = (const float*)d_in[o + 0];
        P.br[s].cb  = (const float*)d_in[o + 1];
        P.br[s].xpw = (const float*)d_in[o + 2];
        P.br[s].dtw = (const float*)d_in[o + 3];
        P.br[s].dtb = (const float*)d_in[o + 4];
        P.br[s].Al  = (const float*)d_in[o + 5];
        P.br[s].Dp  = (const float*)d_in[o + 6];
    }
    float *p_xz, *p_dbc;
    cudaGetSymbolAddress((void**)&p_xz,  g_xz);
    cudaGetSymbolAddress((void**)&p_dbc, g_dbc);

    // xz = x @ in_w^T : bf16x3, 128x64 tiles, 272 blocks
    in_gemm_mma<<<dim3(ED2 / 64, (BLT + 127) / 128), 256>>>(x, in_w, p_xz);

    // per-branch permuted depthwise conv + SiLU — 1368 blocks
    conv_silu<<<NBR * BB * (LSEQ / CONV_T), 512>>>(P);

    // dBC = xa @ xp_w^T : bf16x3, split-K(4), 528 blocks
    cudaMemsetAsync(p_dbc, 0, (size_t)NBR * BLT * DBCW * sizeof(float));
    dbc_mma<<<dim3(NBR, (BLT + 63) / 64, 4), 256>>>(P);

    // chunked selective scan — 864 / 128 / 864 blocks (NCHK=27)
    scan1<<<NBR * BB * NCHK * 4, 128>>>(P);
    scan2<<<NBR * BB * NS, EDI>>>();
    scan3<<<NBR * BB * NCHK * 4, 128>>>(P);

    // combine permuted branch outputs into y — 2052 blocks, float4
    combine_k<<<BLT, 128>>>();

    // out = y @ out_w^T : bf16x3, split-K(2), 264 blocks
    cudaMemsetAsync(d_out, 0, (size_t)BLT * DMO * sizeof(float));
    out_gemm_mma<<<dim3(DMO / 64, (BLT + 63) / 64, 2), 256>>>(out_w, (float*)d_out);
}

// round 15
// speedup vs baseline: 1.0664x; 1.0664x over previous
#include <cuda_runtime.h>
#include <cuda_bf16.h>
#include <math.h>
#include <stdint.h>

#define LSEQ 1026
#define BB   2
#define BLT  (BB*LSEQ)   // 2052
#define DMO  256
#define EDI  512
#define ED2  1024
#define NS   16
#define RRW  16
#define DBCW 48
#define NBR  4
#define NCHK 18
#define CLEN 57          // 18*57 = 1026
#define EQ   128
#define TSTR 17          // uint2 per tile row (17*8=136B)

// ------------------------- scratch -------------------------------------------
__device__ float g_xz[(size_t)BLT*ED2];
__device__ float g_xa[NBR][(size_t)BLT*EDI];
__device__ float g_dbc[NBR][(size_t)BLT*DBCW];
__device__ float g_sum[(size_t)NBR*BB*NCHK*32*EDI];
__device__ float g_h0[(size_t)NBR*BB*NCHK*NS*EDI];
__device__ float g_g[NBR][(size_t)BLT*EDI];
__device__ float g_y[(size_t)BLT*EDI];
__device__ int   g_fast[NBR];

struct BranchPtrs { const float *cw,*cb,*xpw,*dtw,*dtb,*Al,*Dp; };
struct AllPtrs { BranchPtrs br[NBR]; };

// ------------------------- index maps -----------------------------------------
__device__ __forceinline__ int pi_map(int p) {
    if (p == 0 || p == LSEQ - 1) return p;
    int q = p - 1;
    int i = q >> 5, j = q & 31;
    return (j << 5) + i + 1;
}
__device__ __forceinline__ int in_row(int s, int p) {
    if (s == 0) return p;
    if (s == 1) return LSEQ - 1 - p;
    if (s == 2) return pi_map(p);
    return pi_map(LSEQ - 1 - p);
}

// ------------------------- bf16x2 split helpers --------------------------------
__device__ __forceinline__ void split_pair(float x0, float x1, uint32_t& hp, uint32_t& lp) {
    __nv_bfloat16 h0 = __float2bfloat16_rn(x0);
    __nv_bfloat16 h1 = __float2bfloat16_rn(x1);
    float r0 = x0 - __bfloat162float(h0);
    float r1 = x1 - __bfloat162float(h1);
    __nv_bfloat16 l0 = __float2bfloat16_rn(r0);
    __nv_bfloat16 l1 = __float2bfloat16_rn(r1);
    hp = ((uint32_t)__bfloat16_as_ushort(h1) << 16) | (uint32_t)__bfloat16_as_ushort(h0);
    lp = ((uint32_t)__bfloat16_as_ushort(l1) << 16) | (uint32_t)__bfloat16_as_ushort(l0);
}
__device__ __forceinline__ void mma_bf16(float c[4], const uint32_t a[4],
                                         uint32_t b0, uint32_t b1) {
    asm volatile("mma.sync.aligned.m16n8k16.row.col.f32.bf16.bf16.f32 "
        "{%0,%1,%2,%3}, {%4,%5,%6,%7}, {%8,%9}, {%0,%1,%2,%3};"
        : "+f"(c[0]), "+f"(c[1]), "+f"(c[2]), "+f"(c[3])
        : "r"(a[0]), "r"(a[1]), "r"(a[2]), "r"(a[3]), "r"(b0), "r"(b1));
}
__device__ __forceinline__ int swz(int row, int p) { return p ^ ((row & 7) << 1); }
__device__ __forceinline__ void store8(uint2* T, int row, int ka, float4 v0, float4 v1) {
    float v[8] = {v0.x, v0.y, v0.z, v0.w, v1.x, v1.y, v1.z, v1.w};
#pragma unroll
    for (int j = 0; j < 4; j++) {
        uint32_t hp, lp;
        split_pair(v[2*j], v[2*j+1], hp, lp);
        int p = (ka >> 1) + j;
        T[row * TSTR + swz(row, p)] = make_uint2(hp, lp);
    }
}
__device__ __forceinline__ void lda_frag(const uint2* T, int r0, int kk, int t4,
                                         uint32_t ah[4], uint32_t al[4]) {
    uint2 q0 = T[r0 * TSTR + swz(r0, kk*8 + t4)];
    uint2 q1 = T[(r0+8) * TSTR + swz(r0+8, kk*8 + t4)];
    uint2 q2 = T[r0 * TSTR + swz(r0, kk*8 + t4 + 4)];
    uint2 q3 = T[(r0+8) * TSTR + swz(r0+8, kk*8 + t4 + 4)];
    ah[0]=q0.x; ah[1]=q1.x; ah[2]=q2.x; ah[3]=q3.x;
    al[0]=q0.y; al[1]=q1.y; al[2]=q2.y; al[3]=q3.y;
}
__device__ __forceinline__ void mma3(const uint2* Bt, int n, int kk, int t4,
                                     const uint32_t ah[4], const uint32_t al[4],
                                     float acc[4]) {
    uint2 p0 = Bt[n * TSTR + swz(n, kk*8 + t4)];
    uint2 p1 = Bt[n * TSTR + swz(n, kk*8 + t4 + 4)];
    mma_bf16(acc, ah, p0.y, p1.y);
    mma_bf16(acc, al, p0.x, p1.x);
    mma_bf16(acc, ah, p0.x, p1.x);
}

// ====== in-GEMM (bf16x3): xz = x @ in_w^T. 128x64 tile, K=256, 272 blocks ===
__global__ __launch_bounds__(256)
void in_gemm_mma(const float* __restrict__ A, const float* __restrict__ Bm,
                 float* __restrict__ C) {
    __shared__ uint2 At[128 * TSTR];
    __shared__ uint2 Bt[64 * TSTR];
    int tid = threadIdx.x;
    int n0 = blockIdx.x * 64, m0 = blockIdx.y * 128;
    int ra = tid >> 1, ka = (tid & 1) * 16;
    bool mok = (m0 + ra) < BLT;
    const float* Ap = A + (size_t)(m0 + ra) * DMO + ka;
    int rb = tid >> 2, kb = (tid & 3) * 8;
    const float* Bp = Bm + (size_t)(n0 + rb) * DMO + kb;
    int lane = tid & 31, wid = tid >> 5;
    int g = lane >> 2, t4 = lane & 3;
    int wm = (wid & 3) * 32, wn = (wid >> 2) * 32;

    float4 a[4], b[2];
#pragma unroll
    for (int i = 0; i < 4; i++)
        a[i] = mok ? *(const float4*)(Ap + 4*i) : make_float4(0,0,0,0);
    b[0] = *(const float4*)Bp; b[1] = *(const float4*)(Bp + 4);

    float acc[2][4][4];
#pragma unroll
    for (int mi = 0; mi < 2; mi++)
#pragma unroll
        for (int ni = 0; ni < 4; ni++)
#pragma unroll
            for (int q = 0; q < 4; q++) acc[mi][ni][q] = 0.f;

#pragma unroll 1
    for (int s = 0; s < 8; s++) {
        store8(At, ra, ka, a[0], a[1]);
        store8(At, ra, ka + 8, a[2], a[3]);
        store8(Bt, rb, kb, b[0], b[1]);
        __syncthreads();
        if (s + 1 < 8) {
            int off = 32 * (s + 1);
#pragma unroll
            for (int i = 0; i < 4; i++)
                a[i] = mok ? *(const float4*)(Ap + off + 4*i) : make_float4(0,0,0,0);
            b[0] = *(const float4*)(Bp + off); b[1] = *(const float4*)(Bp + off + 4);
        }
#pragma unroll
        for (int kk = 0; kk < 2; kk++) {
            uint32_t ah[2][4], al[2][4];
            lda_frag(At, wm + g, kk, t4, ah[0], al[0]);
            lda_frag(At, wm + 16 + g, kk, t4, ah[1], al[1]);
#pragma unroll
            for (int ni = 0; ni < 4; ni++) {
                int n = wn + ni * 8 + g;
                uint2 p0 = Bt[n * TSTR + swz(n, kk*8 + t4)];
                uint2 p1 = Bt[n * TSTR + swz(n, kk*8 + t4 + 4)];
#pragma unroll
                for (int mi = 0; mi < 2; mi++) {
                    mma_bf16(acc[mi][ni], ah[mi], p0.y, p1.y);
                    mma_bf16(acc[mi][ni], al[mi], p0.x, p1.x);
                    mma_bf16(acc[mi][ni], ah[mi], p0.x, p1.x);
                }
            }
        }
        __syncthreads();
    }
#pragma unroll
    for (int mi = 0; mi < 2; mi++)
#pragma unroll
        for (int ni = 0; ni < 4; ni++) {
            int row = m0 + wm + mi * 16 + g;
            int col = n0 + wn + ni * 8 + 2 * t4;
            if (row < BLT)
                *(float2*)&C[(size_t)row * ED2 + col] =
                    make_float2(acc[mi][ni][0], acc[mi][ni][1]);
            if (row + 8 < BLT)
                *(float2*)&C[(size_t)(row + 8) * ED2 + col] =
                    make_float2(acc[mi][ni][2], acc[mi][ni][3]);
        }
}

// ====== dBC (bf16x3): 64x48, split-K(4), 256 thr, atomic ====================
__global__ __launch_bounds__(256)
void dbc_mma(AllPtrs P) {
    __shared__ uint2 At[64 * TSTR];
    __shared__ uint2 Bt[48 * TSTR];
    int tid = threadIdx.x;
    int s = blockIdx.x;
    int m0 = blockIdx.y * 64;
    int kbase = blockIdx.z * 128;
    const float* A  = g_xa[s];
    const float* Bm = P.br[s].xpw;
    float*       C  = g_dbc[s];
    int ra = tid >> 2, ka = (tid & 3) * 8;
    bool mok = (m0 + ra) < BLT;
    const float* Ap = A + (size_t)(m0 + ra) * EDI + kbase + ka;
    bool bok = tid < 192;
    int rb = tid >> 2;
    const float* Bp = Bm + (size_t)rb * EDI + kbase + ka;
    int lane = tid & 31, wid = tid >> 5;
    int g = lane >> 2, t4 = lane & 3;
    int wm = (wid & 3) * 16, wn = (wid >> 2) * 24;

    float4 a[2], b[2];
    a[0] = mok ? *(const float4*)Ap : make_float4(0,0,0,0);
    a[1] = mok ? *(const float4*)(Ap + 4) : make_float4(0,0,0,0);
    b[0] = bok ? *(const float4*)Bp : make_float4(0,0,0,0);
    b[1] = bok ? *(const float4*)(Bp + 4) : make_float4(0,0,0,0);

    float acc[3][4];
#pragma unroll
    for (int ni = 0; ni < 3; ni++)
#pragma unroll
        for (int q = 0; q < 4; q++) acc[ni][q] = 0.f;

#pragma unroll 1
    for (int s2 = 0; s2 < 4; s2++) {
        store8(At, ra, ka, a[0], a[1]);
        if (bok) store8(Bt, rb, ka, b[0], b[1]);
        __syncthreads();
        if (s2 + 1 < 4) {
            int off = 32 * (s2 + 1);
            a[0] = mok ? *(const float4*)(Ap + off) : make_float4(0,0,0,0);
            a[1] = mok ? *(const float4*)(Ap + off + 4) : make_float4(0,0,0,0);
            b[0] = bok ? *(const float4*)(Bp + off) : make_float4(0,0,0,0);
            b[1] = bok ? *(const float4*)(Bp + off + 4) : make_float4(0,0,0,0);
        }
#pragma unroll
        for (int kk = 0; kk < 2; kk++) {
            uint32_t ah[4], al[4];
            lda_frag(At, wm + g, kk, t4, ah, al);
#pragma unroll
            for (int ni = 0; ni < 3; ni++)
                mma3(Bt, wn + ni * 8 + g, kk, t4, ah, al, acc[ni]);
        }
        __syncthreads();
    }
#pragma unroll
    for (int ni = 0; ni < 3; ni++) {
        int row = m0 + wm + g;
        int col = wn + ni * 8 + 2 * t4;
        if (row < BLT) {
            atomicAdd(&C[(size_t)row * DBCW + col], acc[ni][0]);
            atomicAdd(&C[(size_t)row * DBCW + col + 1], acc[ni][1]);
        }
        if (row + 8 < BLT) {
            atomicAdd(&C[(size_t)(row + 8) * DBCW + col], acc[ni][2]);
            atomicAdd(&C[(size_t)(row + 8) * DBCW + col + 1], acc[ni][3]);
        }
    }
}

// ====== out-GEMM (bf16x3): y @ out_w^T. 64x64, split-K(2), atomic ===========
__global__ __launch_bounds__(256)
void out_gemm_mma(const float* __restrict__ out_w, float* __restrict__ C) {
    __shared__ uint2 At[64 * TSTR];
    __shared__ uint2 Bt[64 * TSTR];
    int tid = threadIdx.x;
    int n0 = blockIdx.x * 64, m0 = blockIdx.y * 64;
    int kbase = blockIdx.z * 256;
    int ra = tid >> 2, ka = (tid & 3) * 8;
    bool mok = (m0 + ra) < BLT;
    const float* Ap = g_y + (size_t)(m0 + ra) * EDI + kbase + ka;
    const float* Bp = out_w + (size_t)(n0 + ra) * EDI + kbase + ka;
    int lane = tid & 31, wid = tid >> 5;
    int g = lane >> 2, t4 = lane & 3;
    int wm = (wid & 3) * 16, wn = (wid >> 2) * 32;

    float4 a[2], b[2];
    a[0] = mok ? *(const float4*)Ap : make_float4(0,0,0,0);
    a[1] = mok ? *(const float4*)(Ap + 4) : make_float4(0,0,0,0);
    b[0] = *(const float4*)Bp; b[1] = *(const float4*)(Bp + 4);

    float acc[4][4];
#pragma unroll
    for (int ni = 0; ni < 4; ni++)
#pragma unroll
        for (int q = 0; q < 4; q++) acc[ni][q] = 0.f;

#pragma unroll 1
    for (int s2 = 0; s2 < 8; s2++) {
        store8(At, ra, ka, a[0], a[1]);
        store8(Bt, ra, ka, b[0], b[1]);
        __syncthreads();
        if (s2 + 1 < 8) {
            int off = 32 * (s2 + 1);
            a[0] = mok ? *(const float4*)(Ap + off) : make_float4(0,0,0,0);
            a[1] = mok ? *(const float4*)(Ap + off + 4) : make_float4(0,0,0,0);
            b[0] = *(const float4*)(Bp + off); b[1] = *(const float4*)(Bp + off + 4);
        }
#pragma unroll
        for (int kk = 0; kk < 2; kk++) {
            uint32_t ah[4], al[4];
            lda_frag(At, wm + g, kk, t4, ah, al);
#pragma unroll
            for (int ni = 0; ni < 4; ni++)
                mma3(Bt, wn + ni * 8 + g, kk, t4, ah, al, acc[ni]);
        }
        __syncthreads();
    }
#pragma unroll
    for (int ni = 0; ni < 4; ni++) {
        int row = m0 + wm + g;
        int col = n0 + wn + ni * 8 + 2 * t4;
        if (row < BLT) {
            atomicAdd(&C[(size_t)row * DMO + col], acc[ni][0]);
            atomicAdd(&C[(size_t)row * DMO + col + 1], acc[ni][1]);
        }
        if (row + 8 < BLT) {
            atomicAdd(&C[(size_t)(row + 8) * DMO + col], acc[ni][2]);
            atomicAdd(&C[(size_t)(row + 8) * DMO + col + 1], acc[ni][3]);
        }
    }
}

// ---------- combine: y = 0.25*(g0 + rev(g1) + cross(g2) + revcross(g3)) -----
__global__ __launch_bounds__(128)
void combine_k() {
    int bl = blockIdx.x;
    int b = bl / LSEQ, l = bl % LSEQ;
    int e4 = threadIdx.x * 4;
    size_t r0 = (size_t)bl * EDI + e4;
    size_t r1 = (size_t)(b * LSEQ + (LSEQ - 1 - l)) * EDI + e4;
    size_t r2 = (size_t)(b * LSEQ + pi_map(l)) * EDI + e4;
    size_t r3 = (size_t)(b * LSEQ + pi_map(LSEQ - 1 - l)) * EDI + e4;
    float4 p0 = *(const float4*)(g_g[0] + r0);
    float4 p1 = *(const float4*)(g_g[1] + r1);
    float4 p2 = *(const float4*)(g_g[2] + r2);
    float4 p3 = *(const float4*)(g_g[3] + r3);
    float4 o;
    o.x = 0.25f * (p0.x + p1.x + p2.x + p3.x);
    o.y = 0.25f * (p0.y + p1.y + p2.y + p3.y);
    o.z = 0.25f * (p0.z + p1.z + p2.z + p3.z);
    o.w = 0.25f * (p0.w + p1.w + p2.w + p3.w);
    *(float4*)(g_y + r0) = o;
}

// ------------------------- structure check for A = -(n+1) -------------------
__global__ void flag_kernel(AllPtrs P) {
    __shared__ int ok;
    int s = blockIdx.x;
    if (threadIdx.x == 0) ok = 1;
    __syncthreads();
    const float* Al = P.br[s].Al;
    int e = threadIdx.x;
    bool good = true;
#pragma unroll
    for (int n = 0; n < NS; n++) {
        float ref = logf((float)(n + 1));
        if (fabsf(Al[e * NS + n] - ref) > 1e-5f * fmaxf(1.f, fabsf(ref))) good = false;
    }
    if (!good) atomicAnd(&ok, 0);
    __syncthreads();
    if (threadIdx.x == 0) g_fast[s] = ok;
}

// ------- depthwise conv (K=4 causal) + SiLU ---------------------------------
#define CONV_T 6
__global__ __launch_bounds__(512)
void conv_silu(AllPtrs P) {
    int blk = blockIdx.x;
    int ntile = LSEQ / CONV_T;
    int s  = blk / (BB * ntile);
    int rm = blk % (BB * ntile);
    int b  = rm / ntile;
    int l0 = (rm % ntile) * CONV_T;
    int e  = threadIdx.x;
    float4 cwv = *(const float4*)(P.br[s].cw + e * 4);
    float cb = P.br[s].cb[e];
    float v0 = 0.f, v1 = 0.f, v2 = 0.f;
    if (l0 - 3 >= 0) v0 = g_xz[(size_t)(b * LSEQ + in_row(s, l0 - 3)) * ED2 + e];
    if (l0 - 2 >= 0) v1 = g_xz[(size_t)(b * LSEQ + in_row(s, l0 - 2)) * ED2 + e];
    if (l0 - 1 >= 0) v2 = g_xz[(size_t)(b * LSEQ + in_row(s, l0 - 1)) * ED2 + e];
#pragma unroll
    for (int t = 0; t < CONV_T; t++) {
        int l = l0 + t;
        float v3 = g_xz[(size_t)(b * LSEQ + in_row(s, l)) * ED2 + e];
        float acc = cb;
        acc = fmaf(cwv.x, v0, acc);
        acc = fmaf(cwv.y, v1, acc);
        acc = fmaf(cwv.z, v2, acc);
        acc = fmaf(cwv.w, v3, acc);
        float sg = 1.f / (1.f + __expf(-acc));
        g_xa[s][(size_t)(b * LSEQ + l) * EDI + e] = acc * sg;
        v0 = v1; v1 = v2; v2 = v3;
    }
}

// -------- scan phase 1: chunk summaries, delta fused, channel-quarter -------
__global__ __launch_bounds__(128)
void scan1(AllPtrs P) {
    __shared__ float f_s[CLEN][NS];
    __shared__ float Bsm[CLEN * NS];
    int blk = blockIdx.x;
    int quarter = blk & 3;
    int blk2 = blk >> 2;
    int s = blk2 / (BB * NCHK);
    int rem = blk2 % (BB * NCHK);
    int b = rem / NCHK, c = rem % NCHK;
    int e0 = quarter * EQ;
    int e = e0 + threadIdx.x;
    for (int idx = threadIdx.x; idx < CLEN * 32; idx += blockDim.x) {
        int t = idx >> 5, q = idx & 31;
        float v = g_dbc[s][(size_t)(b * LSEQ + c * CLEN + t) * DBCW + q];
        if (q < 16) f_s[t][q] = v;
        else        Bsm[t * NS + (q - 16)] = v;
    }
    // direct per-thread weight row load (contiguous 64B)
    const float* dtw = P.br[s].dtw + (size_t)e * RRW;
    float w[RRW];
    {
        float4 w0 = *(const float4*)dtw;
        float4 w1 = *(const float4*)(dtw + 4);
        float4 w2 = *(const float4*)(dtw + 8);
        float4 w3 = *(const float4*)(dtw + 12);
        w[0]=w0.x; w[1]=w0.y; w[2]=w0.z; w[3]=w0.w;
        w[4]=w1.x; w[5]=w1.y; w[6]=w1.z; w[7]=w1.w;
        w[8]=w2.x; w[9]=w2.y; w[10]=w2.z; w[11]=w2.w;
        w[12]=w3.x; w[13]=w3.y; w[14]=w3.z; w[15]=w3.w;
    }
    float dtb = P.br[s].dtb[e];
    int fast = g_fast[s];
    float A_[NS];
    if (!fast) {
        const float* Al = P.br[s].Al;
#pragma unroll
        for (int n = 0; n < NS; n++) A_[n] = -__expf(Al[e * NS + n]);
    }
    __syncthreads();
    float h[NS], Pn[NS];
#pragma unroll
    for (int n = 0; n < NS; n++) { h[n] = 0.f; Pn[n] = 1.f; }
    float Rp = 1.f;
    const float* xptr = g_xa[s] + (size_t)(b * LSEQ + c * CLEN) * EDI + e;
    float x_cur = *xptr;
    const float* xn = xptr + EDI;
    for (int t = 0; t < CLEN; t++) {
        float x_nxt = (t + 1 < CLEN) ? *xn : 0.f;
        xn += EDI;
        float u0 = dtb, u1 = 0.f, u2 = 0.f, u3 = 0.f;
#pragma unroll
        for (int q = 0; q < RRW; q += 4) {
            u0 = fmaf(f_s[t][q],   w[q],   u0);
            u1 = fmaf(f_s[t][q+1], w[q+1], u1);
            u2 = fmaf(f_s[t][q+2], w[q+2], u2);
            u3 = fmaf(f_s[t][q+3], w[q+3], u3);
        }
        float u = (u0 + u1) + (u2 + u3);
        float d = fmaxf(u, 0.f) + __logf(1.f + __expf(-fabsf(u)));
        float dx = d * x_cur;
        if (fast) {
            float r = __expf(-d);
            Rp *= r;
            float dA = 1.f;
#pragma unroll
            for (int n = 0; n < NS; n++) {
                dA *= r;
                h[n] = fmaf(dA, h[n], dx * Bsm[t * NS + n]);
            }
        } else {
#pragma unroll
            for (int n = 0; n < NS; n++) {
                float dA = __expf(d * A_[n]);
                Pn[n] *= dA;
                h[n] = fmaf(dA, h[n], dx * Bsm[t * NS + n]);
            }
        }
        x_cur = x_nxt;
    }
    if (fast) {
        float q = 1.f;
#pragma unroll
        for (int n = 0; n < NS; n++) { q *= Rp; Pn[n] = q; }
    }
    size_t base = (size_t)((s * BB + b) * NCHK + c) * 32 * EDI + e;
#pragma unroll
    for (int n = 0; n < NS; n++) g_sum[base + (size_t)n * EDI] = h[n];
#pragma unroll
    for (int n = 0; n < NS; n++) g_sum[base + (size_t)(16 + n) * EDI] = Pn[n];
}

// ---------- scan phase 2: chunk combine, all loads prefetched ---------------
__global__ __launch_bounds__(512)
void scan2() {
    int n = blockIdx.x & 15;
    int sb = blockIdx.x >> 4;
    int e = threadIdx.x;
    float hl[NCHK], Pv[NCHK];
#pragma unroll
    for (int c = 0; c < NCHK; c++) {
        size_t pb = (size_t)(sb * NCHK + c) * 32 * EDI + e;
        hl[c] = g_sum[pb + (size_t)n * EDI];
        Pv[c] = g_sum[pb + (size_t)(16 + n) * EDI];
    }
    float h = 0.f;
#pragma unroll
    for (int c = 0; c < NCHK; c++) {
        g_h0[(size_t)(sb * NCHK + c) * NS * EDI + (size_t)n * EDI + e] = h;
        h = fmaf(Pv[c], h, hl[c]);
    }
}

// -------- scan phase 3: full walk + gate, delta fused, channel-quarter ------
__global__ __launch_bounds__(128)
void scan3(AllPtrs P) {
    __shared__ float f_s[CLEN][NS];
    __shared__ float Bsm[CLEN * NS];
    __shared__ float Csm[CLEN * NS];
    int blk = blockIdx.x;
    int quarter = blk & 3;
    int blk2 = blk >> 2;
    int s = blk2 / (BB * NCHK);
    int rem = blk2 % (BB * NCHK);
    int b = rem / NCHK, c = rem % NCHK;
    int e0 = quarter * EQ;
    int e = e0 + threadIdx.x;
    for (int idx = threadIdx.x; idx < CLEN * DBCW; idx += blockDim.x) {
        int t = idx / DBCW, q = idx % DBCW;
        float v = g_dbc[s][(size_t)(b * LSEQ + c * CLEN + t) * DBCW + q];
        if (q < 16)      f_s[t][q] = v;
        else if (q < 32) Bsm[t * NS + (q - 16)] = v;
        else             Csm[t * NS + (q - 32)] = v;
    }
    const float* dtw = P.br[s].dtw + (size_t)e * RRW;
    float w[RRW];
    {
        float4 w0 = *(const float4*)dtw;
        float4 w1 = *(const float4*)(dtw + 4);
        float4 w2 = *(const float4*)(dtw + 8);
        float4 w3 = *(const float4*)(dtw + 12);
        w[0]=w0.x; w[1]=w0.y; w[2]=w0.z; w[3]=w0.w;
        w[4]=w1.x; w[5]=w1.y; w[6]=w1.z; w[7]=w1.w;
        w[8]=w2.x; w[9]=w2.y; w[10]=w2.z; w[11]=w2.w;
        w[12]=w3.x; w[13]=w3.y; w[14]=w3.z; w[15]=w3.w;
    }
    float dtb = P.br[s].dtb[e];
    int fast = g_fast[s];
    float A_[NS];
    if (!fast) {
        const float* Al = P.br[s].Al;
#pragma unroll
        for (int n = 0; n < NS; n++) A_[n] = -__expf(Al[e * NS + n]);
    }
    float Dv = P.br[s].Dp[e];
    float h[NS];
    {
        size_t sb = (size_t)((s * BB + b) * NCHK + c);
        size_t hb = sb * NS * EDI + e;
#pragma unroll
        for (int n = 0; n < NS; n++) h[n] = g_h0[hb + (size_t)n * EDI];
    }
    __syncthreads();
    int l0 = c * CLEN;
    size_t bbase = (size_t)(b * LSEQ);
    const float* xptr = g_xa[s] + (size_t)(bbase + l0) * EDI + e;
    float* gout = g_g[s] + (size_t)(bbase + l0) * EDI + e;
    float x_cur = *xptr;
    const float* xn = xptr + EDI;
    float za_cur = g_xz[(bbase + in_row(s, l0)) * ED2 + EDI + e];
    for (int t = 0; t < CLEN; t++) {
        float x_nxt = 0.f, za_nxt = 0.f;
        if (t + 1 < CLEN) {
            x_nxt = *xn;
            za_nxt = g_xz[(bbase + in_row(s, l0 + t + 1)) * ED2 + EDI + e];
        }
        xn += EDI;
        float u0 = dtb, u1 = 0.f, u2 = 0.f, u3 = 0.f;
#pragma unroll
        for (int q = 0; q < RRW; q += 4) {
            u0 = fmaf(f_s[t][q],   w[q],   u0);
            u1 = fmaf(f_s[t][q+1], w[q+1], u1);
            u2 = fmaf(f_s[t][q+2], w[q+2], u2);
            u3 = fmaf(f_s[t][q+3], w[q+3], u3);
        }
        float u = (u0 + u1) + (u2 + u3);
        float d = fmaxf(u, 0.f) + __logf(1.f + __expf(-fabsf(u)));
        float dx = d * x_cur;
        float acc = Dv * x_cur;
        if (fast) {
            float r = __expf(-d);
            float dA = 1.f;
#pragma unroll
            for (int n = 0; n < NS; n++) {
                dA *= r;
                h[n] = fmaf(dA, h[n], dx * Bsm[t * NS + n]);
                acc = fmaf(h[n], Csm[t * NS + n], acc);
            }
        } else {
#pragma unroll
            for (int n = 0; n < NS; n++) {
                float dA = __expf(d * A_[n]);
                h[n] = fmaf(dA, h[n], dx * Bsm[t * NS + n]);
                acc = fmaf(h[n], Csm[t * NS + n], acc);
            }
        }
        float sz = za_cur / (1.f + __expf(-za_cur));
        *gout = acc * sz;
        gout += EDI;
        x_cur = x_nxt; za_cur = za_nxt;
    }
}

// ------------------------- launch ------------------------------------------
extern "C" void kernel_launch(void* const* d_in, const int* in_sizes, int n_in,
                              void* d_out, int out_size) {
    const float* x     = (const float*)d_in[0];
    const float* in_w  = (const float*)d_in[1];
    const float* out_w = (const float*)d_in[2];
    AllPtrs P;
    for (int s = 0; s < NBR; s++) {
        int o = 3 + 7 * s;
        P.br[s].cw  = (const float*)d_in[o + 0];
        P.br[s].cb  = (const float*)d_in[o + 1];
        P.br[s].xpw = (const float*)d_in[o + 2];
        P.br[s].dtw = (const float*)d_in[o + 3];
        P.br[s].dtb = (const float*)d_in[o + 4];
        P.br[s].Al  = (const float*)d_in[o + 5];
        P.br[s].Dp  = (const float*)d_in[o + 6];
    }
    float *p_xz, *p_dbc;
    cudaGetSymbolAddress((void**)&p_xz,  g_xz);
    cudaGetSymbolAddress((void**)&p_dbc, g_dbc);

    flag_kernel<<<NBR, EDI>>>(P);

    // xz = x @ in_w^T : bf16x3, 128x64 tiles, 272 blocks
    in_gemm_mma<<<dim3(ED2 / 64, (BLT + 127) / 128), 256>>>(x, in_w, p_xz);

    // per-branch permuted depthwise conv + SiLU — 1368 blocks
    conv_silu<<<NBR * BB * (LSEQ / CONV_T), 512>>>(P);

    // dBC = xa @ xp_w^T : bf16x3, split-K(4), 528 blocks
    cudaMemsetAsync(p_dbc, 0, (size_t)NBR * BLT * DBCW * sizeof(float));
    dbc_mma<<<dim3(NBR, (BLT + 63) / 64, 4), 256>>>(P);

    // chunked selective scan — 576 / 128 / 576 blocks (NCHK=18)
    scan1<<<NBR * BB * NCHK * 4, 128>>>(P);
    scan2<<<NBR * BB * NS, EDI>>>();
    scan3<<<NBR * BB * NCHK * 4, 128>>>(P);

    // combine permuted branch outputs into y — 2052 blocks, float4
    combine_k<<<BLT, 128>>>();

    // out = y @ out_w^T : bf16x3, split-K(2), 264 blocks
    cudaMemsetAsync(d_out, 0, (size_t)BLT * DMO * sizeof(float));
    out_gemm_mma<<<dim3(DMO / 64, (BLT + 63) / 64, 2), 256>>>(out_w, (float*)d_out);
}

// round 16
// speedup vs baseline: 1.0802x; 1.0129x over previous
#include <cuda_runtime.h>
#include <cuda_bf16.h>
#include <math.h>
#include <stdint.h>

#define LSEQ 1026
#define BB   2
#define BLT  (BB*LSEQ)   // 2052
#define DMO  256
#define EDI  512
#define ED2  1024
#define NS   16
#define RRW  16
#define DBCW 48
#define NBR  4
#define NCHK 18
#define CLEN 57          // 18*57 = 1026
#define EQ   128
#define TSTR 17          // uint2 per tile row (17*8=136B)

// ------------------------- scratch -------------------------------------------
__device__ float g_xz[(size_t)BLT*ED2];
__device__ float g_xa[NBR][(size_t)BLT*EDI];
__device__ float g_dbc[NBR][(size_t)BLT*DBCW];
__device__ float g_sum[(size_t)NBR*BB*NCHK*32*EDI];
__device__ float g_h0[(size_t)NBR*BB*NCHK*NS*EDI];
__device__ float g_g[NBR][(size_t)BLT*EDI];
__device__ float g_y[(size_t)BLT*EDI];
__device__ int   g_fast[NBR];

struct BranchPtrs { const float *cw,*cb,*xpw,*dtw,*dtb,*Al,*Dp; };
struct AllPtrs { BranchPtrs br[NBR]; };

// ------------------------- index maps -----------------------------------------
__device__ __forceinline__ int pi_map(int p) {
    if (p == 0 || p == LSEQ - 1) return p;
    int q = p - 1;
    int i = q >> 5, j = q & 31;
    return (j << 5) + i + 1;
}
__device__ __forceinline__ int in_row(int s, int p) {
    if (s == 0) return p;
    if (s == 1) return LSEQ - 1 - p;
    if (s == 2) return pi_map(p);
    return pi_map(LSEQ - 1 - p);
}

// ------------------------- bf16x2 split helpers --------------------------------
__device__ __forceinline__ void split_pair(float x0, float x1, uint32_t& hp, uint32_t& lp) {
    __nv_bfloat16 h0 = __float2bfloat16_rn(x0);
    __nv_bfloat16 h1 = __float2bfloat16_rn(x1);
    float r0 = x0 - __bfloat162float(h0);
    float r1 = x1 - __bfloat162float(h1);
    __nv_bfloat16 l0 = __float2bfloat16_rn(r0);
    __nv_bfloat16 l1 = __float2bfloat16_rn(r1);
    hp = ((uint32_t)__bfloat16_as_ushort(h1) << 16) | (uint32_t)__bfloat16_as_ushort(h0);
    lp = ((uint32_t)__bfloat16_as_ushort(l1) << 16) | (uint32_t)__bfloat16_as_ushort(l0);
}
__device__ __forceinline__ void mma_bf16(float c[4], const uint32_t a[4],
                                         uint32_t b0, uint32_t b1) {
    asm volatile("mma.sync.aligned.m16n8k16.row.col.f32.bf16.bf16.f32 "
        "{%0,%1,%2,%3}, {%4,%5,%6,%7}, {%8,%9}, {%0,%1,%2,%3};"
        : "+f"(c[0]), "+f"(c[1]), "+f"(c[2]), "+f"(c[3])
        : "r"(a[0]), "r"(a[1]), "r"(a[2]), "r"(a[3]), "r"(b0), "r"(b1));
}
__device__ __forceinline__ int swz(int row, int p) { return p ^ ((row & 7) << 1); }
__device__ __forceinline__ void store8(uint2* T, int row, int ka, float4 v0, float4 v1) {
    float v[8] = {v0.x, v0.y, v0.z, v0.w, v1.x, v1.y, v1.z, v1.w};
#pragma unroll
    for (int j = 0; j < 4; j++) {
        uint32_t hp, lp;
        split_pair(v[2*j], v[2*j+1], hp, lp);
        int p = (ka >> 1) + j;
        T[row * TSTR + swz(row, p)] = make_uint2(hp, lp);
    }
}
__device__ __forceinline__ void lda_frag(const uint2* T, int r0, int kk, int t4,
                                         uint32_t ah[4], uint32_t al[4]) {
    uint2 q0 = T[r0 * TSTR + swz(r0, kk*8 + t4)];
    uint2 q1 = T[(r0+8) * TSTR + swz(r0+8, kk*8 + t4)];
    uint2 q2 = T[r0 * TSTR + swz(r0, kk*8 + t4 + 4)];
    uint2 q3 = T[(r0+8) * TSTR + swz(r0+8, kk*8 + t4 + 4)];
    ah[0]=q0.x; ah[1]=q1.x; ah[2]=q2.x; ah[3]=q3.x;
    al[0]=q0.y; al[1]=q1.y; al[2]=q2.y; al[3]=q3.y;
}
__device__ __forceinline__ void mma3(const uint2* Bt, int n, int kk, int t4,
                                     const uint32_t ah[4], const uint32_t al[4],
                                     float acc[4]) {
    uint2 p0 = Bt[n * TSTR + swz(n, kk*8 + t4)];
    uint2 p1 = Bt[n * TSTR + swz(n, kk*8 + t4 + 4)];
    mma_bf16(acc, ah, p0.y, p1.y);
    mma_bf16(acc, al, p0.x, p1.x);
    mma_bf16(acc, ah, p0.x, p1.x);
}
// log-depth powers p[n] = r^(n+1), n=0..15
__device__ __forceinline__ void pow_tree(float r, float p[16]) {
    p[0] = r;
    p[1] = r * r;
    p[2] = p[1] * r;    p[3] = p[1] * p[1];
    p[4] = p[3] * r;    p[5] = p[2] * p[2];  p[6] = p[3] * p[2];  p[7] = p[3] * p[3];
    p[8]  = p[7] * r;     p[9]  = p[7] * p[1]; p[10] = p[7] * p[2];
    p[11] = p[7] * p[3];  p[12] = p[7] * p[4]; p[13] = p[7] * p[5];
    p[14] = p[7] * p[6];  p[15] = p[7] * p[7];
}

// ====== in-GEMM (bf16x3): xz = x @ in_w^T. 128x64 tile, K=256, 272 blocks ===
__global__ __launch_bounds__(256)
void in_gemm_mma(const float* __restrict__ A, const float* __restrict__ Bm,
                 float* __restrict__ C) {
    __shared__ uint2 At[128 * TSTR];
    __shared__ uint2 Bt[64 * TSTR];
    int tid = threadIdx.x;
    int n0 = blockIdx.x * 64, m0 = blockIdx.y * 128;
    int ra = tid >> 1, ka = (tid & 1) * 16;
    bool mok = (m0 + ra) < BLT;
    const float* Ap = A + (size_t)(m0 + ra) * DMO + ka;
    int rb = tid >> 2, kb = (tid & 3) * 8;
    const float* Bp = Bm + (size_t)(n0 + rb) * DMO + kb;
    int lane = tid & 31, wid = tid >> 5;
    int g = lane >> 2, t4 = lane & 3;
    int wm = (wid & 3) * 32, wn = (wid >> 2) * 32;

    float4 a[4], b[2];
#pragma unroll
    for (int i = 0; i < 4; i++)
        a[i] = mok ? *(const float4*)(Ap + 4*i) : make_float4(0,0,0,0);
    b[0] = *(const float4*)Bp; b[1] = *(const float4*)(Bp + 4);

    float acc[2][4][4];
#pragma unroll
    for (int mi = 0; mi < 2; mi++)
#pragma unroll
        for (int ni = 0; ni < 4; ni++)
#pragma unroll
            for (int q = 0; q < 4; q++) acc[mi][ni][q] = 0.f;

#pragma unroll 1
    for (int s = 0; s < 8; s++) {
        store8(At, ra, ka, a[0], a[1]);
        store8(At, ra, ka + 8, a[2], a[3]);
        store8(Bt, rb, kb, b[0], b[1]);
        __syncthreads();
        if (s + 1 < 8) {
            int off = 32 * (s + 1);
#pragma unroll
            for (int i = 0; i < 4; i++)
                a[i] = mok ? *(const float4*)(Ap + off + 4*i) : make_float4(0,0,0,0);
            b[0] = *(const float4*)(Bp + off); b[1] = *(const float4*)(Bp + off + 4);
        }
#pragma unroll
        for (int kk = 0; kk < 2; kk++) {
            uint32_t ah[2][4], al[2][4];
            lda_frag(At, wm + g, kk, t4, ah[0], al[0]);
            lda_frag(At, wm + 16 + g, kk, t4, ah[1], al[1]);
#pragma unroll
            for (int ni = 0; ni < 4; ni++) {
                int n = wn + ni * 8 + g;
                uint2 p0 = Bt[n * TSTR + swz(n, kk*8 + t4)];
                uint2 p1 = Bt[n * TSTR + swz(n, kk*8 + t4 + 4)];
#pragma unroll
                for (int mi = 0; mi < 2; mi++) {
                    mma_bf16(acc[mi][ni], ah[mi], p0.y, p1.y);
                    mma_bf16(acc[mi][ni], al[mi], p0.x, p1.x);
                    mma_bf16(acc[mi][ni], ah[mi], p0.x, p1.x);
                }
            }
        }
        __syncthreads();
    }
#pragma unroll
    for (int mi = 0; mi < 2; mi++)
#pragma unroll
        for (int ni = 0; ni < 4; ni++) {
            int row = m0 + wm + mi * 16 + g;
            int col = n0 + wn + ni * 8 + 2 * t4;
            if (row < BLT)
                *(float2*)&C[(size_t)row * ED2 + col] =
                    make_float2(acc[mi][ni][0], acc[mi][ni][1]);
            if (row + 8 < BLT)
                *(float2*)&C[(size_t)(row + 8) * ED2 + col] =
                    make_float2(acc[mi][ni][2], acc[mi][ni][3]);
        }
}

// ====== dBC (bf16x3): 64x48, split-K(4), 256 thr, atomic ====================
__global__ __launch_bounds__(256)
void dbc_mma(AllPtrs P) {
    __shared__ uint2 At[64 * TSTR];
    __shared__ uint2 Bt[48 * TSTR];
    int tid = threadIdx.x;
    int s = blockIdx.x;
    int m0 = blockIdx.y * 64;
    int kbase = blockIdx.z * 128;
    const float* A  = g_xa[s];
    const float* Bm = P.br[s].xpw;
    float*       C  = g_dbc[s];
    int ra = tid >> 2, ka = (tid & 3) * 8;
    bool mok = (m0 + ra) < BLT;
    const float* Ap = A + (size_t)(m0 + ra) * EDI + kbase + ka;
    bool bok = tid < 192;
    int rb = tid >> 2;
    const float* Bp = Bm + (size_t)rb * EDI + kbase + ka;
    int lane = tid & 31, wid = tid >> 5;
    int g = lane >> 2, t4 = lane & 3;
    int wm = (wid & 3) * 16, wn = (wid >> 2) * 24;

    float4 a[2], b[2];
    a[0] = mok ? *(const float4*)Ap : make_float4(0,0,0,0);
    a[1] = mok ? *(const float4*)(Ap + 4) : make_float4(0,0,0,0);
    b[0] = bok ? *(const float4*)Bp : make_float4(0,0,0,0);
    b[1] = bok ? *(const float4*)(Bp + 4) : make_float4(0,0,0,0);

    float acc[3][4];
#pragma unroll
    for (int ni = 0; ni < 3; ni++)
#pragma unroll
        for (int q = 0; q < 4; q++) acc[ni][q] = 0.f;

#pragma unroll 1
    for (int s2 = 0; s2 < 4; s2++) {
        store8(At, ra, ka, a[0], a[1]);
        if (bok) store8(Bt, rb, ka, b[0], b[1]);
        __syncthreads();
        if (s2 + 1 < 4) {
            int off = 32 * (s2 + 1);
            a[0] = mok ? *(const float4*)(Ap + off) : make_float4(0,0,0,0);
            a[1] = mok ? *(const float4*)(Ap + off + 4) : make_float4(0,0,0,0);
            b[0] = bok ? *(const float4*)(Bp + off) : make_float4(0,0,0,0);
            b[1] = bok ? *(const float4*)(Bp + off + 4) : make_float4(0,0,0,0);
        }
#pragma unroll
        for (int kk = 0; kk < 2; kk++) {
            uint32_t ah[4], al[4];
            lda_frag(At, wm + g, kk, t4, ah, al);
#pragma unroll
            for (int ni = 0; ni < 3; ni++)
                mma3(Bt, wn + ni * 8 + g, kk, t4, ah, al, acc[ni]);
        }
        __syncthreads();
    }
#pragma unroll
    for (int ni = 0; ni < 3; ni++) {
        int row = m0 + wm + g;
        int col = wn + ni * 8 + 2 * t4;
        if (row < BLT) {
            atomicAdd(&C[(size_t)row * DBCW + col], acc[ni][0]);
            atomicAdd(&C[(size_t)row * DBCW + col + 1], acc[ni][1]);
        }
        if (row + 8 < BLT) {
            atomicAdd(&C[(size_t)(row + 8) * DBCW + col], acc[ni][2]);
            atomicAdd(&C[(size_t)(row + 8) * DBCW + col + 1], acc[ni][3]);
        }
    }
}

// ====== out-GEMM (bf16x3): y @ out_w^T. 64x64, split-K(2), atomic ===========
__global__ __launch_bounds__(256)
void out_gemm_mma(const float* __restrict__ out_w, float* __restrict__ C) {
    __shared__ uint2 At[64 * TSTR];
    __shared__ uint2 Bt[64 * TSTR];
    int tid = threadIdx.x;
    int n0 = blockIdx.x * 64, m0 = blockIdx.y * 64;
    int kbase = blockIdx.z * 256;
    int ra = tid >> 2, ka = (tid & 3) * 8;
    bool mok = (m0 + ra) < BLT;
    const float* Ap = g_y + (size_t)(m0 + ra) * EDI + kbase + ka;
    const float* Bp = out_w + (size_t)(n0 + ra) * EDI + kbase + ka;
    int lane = tid & 31, wid = tid >> 5;
    int g = lane >> 2, t4 = lane & 3;
    int wm = (wid & 3) * 16, wn = (wid >> 2) * 32;

    float4 a[2], b[2];
    a[0] = mok ? *(const float4*)Ap : make_float4(0,0,0,0);
    a[1] = mok ? *(const float4*)(Ap + 4) : make_float4(0,0,0,0);
    b[0] = *(const float4*)Bp; b[1] = *(const float4*)(Bp + 4);

    float acc[4][4];
#pragma unroll
    for (int ni = 0; ni < 4; ni++)
#pragma unroll
        for (int q = 0; q < 4; q++) acc[ni][q] = 0.f;

#pragma unroll 1
    for (int s2 = 0; s2 < 8; s2++) {
        store8(At, ra, ka, a[0], a[1]);
        store8(Bt, ra, ka, b[0], b[1]);
        __syncthreads();
        if (s2 + 1 < 8) {
            int off = 32 * (s2 + 1);
            a[0] = mok ? *(const float4*)(Ap + off) : make_float4(0,0,0,0);
            a[1] = mok ? *(const float4*)(Ap + off + 4) : make_float4(0,0,0,0);
            b[0] = *(const float4*)(Bp + off); b[1] = *(const float4*)(Bp + off + 4);
        }
#pragma unroll
        for (int kk = 0; kk < 2; kk++) {
            uint32_t ah[4], al[4];
            lda_frag(At, wm + g, kk, t4, ah, al);
#pragma unroll
            for (int ni = 0; ni < 4; ni++)
                mma3(Bt, wn + ni * 8 + g, kk, t4, ah, al, acc[ni]);
        }
        __syncthreads();
    }
#pragma unroll
    for (int ni = 0; ni < 4; ni++) {
        int row = m0 + wm + g;
        int col = n0 + wn + ni * 8 + 2 * t4;
        if (row < BLT) {
            atomicAdd(&C[(size_t)row * DMO + col], acc[ni][0]);
            atomicAdd(&C[(size_t)row * DMO + col + 1], acc[ni][1]);
        }
        if (row + 8 < BLT) {
            atomicAdd(&C[(size_t)(row + 8) * DMO + col], acc[ni][2]);
            atomicAdd(&C[(size_t)(row + 8) * DMO + col + 1], acc[ni][3]);
        }
    }
}

// ---------- combine: y = 0.25*(g0 + rev(g1) + cross(g2) + revcross(g3)) -----
__global__ __launch_bounds__(128)
void combine_k() {
    int bl = blockIdx.x;
    int b = bl / LSEQ, l = bl % LSEQ;
    int e4 = threadIdx.x * 4;
    size_t r0 = (size_t)bl * EDI + e4;
    size_t r1 = (size_t)(b * LSEQ + (LSEQ - 1 - l)) * EDI + e4;
    size_t r2 = (size_t)(b * LSEQ + pi_map(l)) * EDI + e4;
    size_t r3 = (size_t)(b * LSEQ + pi_map(LSEQ - 1 - l)) * EDI + e4;
    float4 p0 = *(const float4*)(g_g[0] + r0);
    float4 p1 = *(const float4*)(g_g[1] + r1);
    float4 p2 = *(const float4*)(g_g[2] + r2);
    float4 p3 = *(const float4*)(g_g[3] + r3);
    float4 o;
    o.x = 0.25f * (p0.x + p1.x + p2.x + p3.x);
    o.y = 0.25f * (p0.y + p1.y + p2.y + p3.y);
    o.z = 0.25f * (p0.z + p1.z + p2.z + p3.z);
    o.w = 0.25f * (p0.w + p1.w + p2.w + p3.w);
    *(float4*)(g_y + r0) = o;
}

// ------------------------- structure check for A = -(n+1) -------------------
__global__ void flag_kernel(AllPtrs P) {
    __shared__ int ok;
    int s = blockIdx.x;
    if (threadIdx.x == 0) ok = 1;
    __syncthreads();
    const float* Al = P.br[s].Al;
    int e = threadIdx.x;
    bool good = true;
#pragma unroll
    for (int n = 0; n < NS; n++) {
        float ref = logf((float)(n + 1));
        if (fabsf(Al[e * NS + n] - ref) > 1e-5f * fmaxf(1.f, fabsf(ref))) good = false;
    }
    if (!good) atomicAnd(&ok, 0);
    __syncthreads();
    if (threadIdx.x == 0) g_fast[s] = ok;
}

// ------- depthwise conv (K=4 causal) + SiLU ---------------------------------
#define CONV_T 6
__global__ __launch_bounds__(512)
void conv_silu(AllPtrs P) {
    int blk = blockIdx.x;
    int ntile = LSEQ / CONV_T;
    int s  = blk / (BB * ntile);
    int rm = blk % (BB * ntile);
    int b  = rm / ntile;
    int l0 = (rm % ntile) * CONV_T;
    int e  = threadIdx.x;
    float4 cwv = *(const float4*)(P.br[s].cw + e * 4);
    float cb = P.br[s].cb[e];
    float v0 = 0.f, v1 = 0.f, v2 = 0.f;
    if (l0 - 3 >= 0) v0 = g_xz[(size_t)(b * LSEQ + in_row(s, l0 - 3)) * ED2 + e];
    if (l0 - 2 >= 0) v1 = g_xz[(size_t)(b * LSEQ + in_row(s, l0 - 2)) * ED2 + e];
    if (l0 - 1 >= 0) v2 = g_xz[(size_t)(b * LSEQ + in_row(s, l0 - 1)) * ED2 + e];
#pragma unroll
    for (int t = 0; t < CONV_T; t++) {
        int l = l0 + t;
        float v3 = g_xz[(size_t)(b * LSEQ + in_row(s, l)) * ED2 + e];
        float acc = cb;
        acc = fmaf(cwv.x, v0, acc);
        acc = fmaf(cwv.y, v1, acc);
        acc = fmaf(cwv.z, v2, acc);
        acc = fmaf(cwv.w, v3, acc);
        float sg = 1.f / (1.f + __expf(-acc));
        g_xa[s][(size_t)(b * LSEQ + l) * EDI + e] = acc * sg;
        v0 = v1; v1 = v2; v2 = v3;
    }
}

// -------- scan phase 1: chunk summaries, delta fused, channel-quarter -------
__global__ __launch_bounds__(128)
void scan1(AllPtrs P) {
    __shared__ float f_s[CLEN][NS];
    __shared__ float Bsm[CLEN * NS];
    int blk = blockIdx.x;
    int quarter = blk & 3;
    int blk2 = blk >> 2;
    int s = blk2 / (BB * NCHK);
    int rem = blk2 % (BB * NCHK);
    int b = rem / NCHK, c = rem % NCHK;
    int e0 = quarter * EQ;
    int e = e0 + threadIdx.x;
    for (int idx = threadIdx.x; idx < CLEN * 32; idx += blockDim.x) {
        int t = idx >> 5, q = idx & 31;
        float v = g_dbc[s][(size_t)(b * LSEQ + c * CLEN + t) * DBCW + q];
        if (q < 16) f_s[t][q] = v;
        else        Bsm[t * NS + (q - 16)] = v;
    }
    const float* dtw = P.br[s].dtw + (size_t)e * RRW;
    float w[RRW];
    {
        float4 w0 = *(const float4*)dtw;
        float4 w1 = *(const float4*)(dtw + 4);
        float4 w2 = *(const float4*)(dtw + 8);
        float4 w3 = *(const float4*)(dtw + 12);
        w[0]=w0.x; w[1]=w0.y; w[2]=w0.z; w[3]=w0.w;
        w[4]=w1.x; w[5]=w1.y; w[6]=w1.z; w[7]=w1.w;
        w[8]=w2.x; w[9]=w2.y; w[10]=w2.z; w[11]=w2.w;
        w[12]=w3.x; w[13]=w3.y; w[14]=w3.z; w[15]=w3.w;
    }
    float dtb = P.br[s].dtb[e];
    int fast = g_fast[s];
    float A_[NS];
    if (!fast) {
        const float* Al = P.br[s].Al;
#pragma unroll
        for (int n = 0; n < NS; n++) A_[n] = -__expf(Al[e * NS + n]);
    }
    __syncthreads();
    float h[NS], Pn[NS];
#pragma unroll
    for (int n = 0; n < NS; n++) { h[n] = 0.f; Pn[n] = 1.f; }
    float Rp = 1.f;
    const float* xptr = g_xa[s] + (size_t)(b * LSEQ + c * CLEN) * EDI + e;
    float x_cur = *xptr;
    const float* xn = xptr + EDI;
    for (int t = 0; t < CLEN; t++) {
        float x_nxt = (t + 1 < CLEN) ? *xn : 0.f;
        xn += EDI;
        float u0 = dtb, u1 = 0.f, u2 = 0.f, u3 = 0.f;
#pragma unroll
        for (int q = 0; q < RRW; q += 4) {
            u0 = fmaf(f_s[t][q],   w[q],   u0);
            u1 = fmaf(f_s[t][q+1], w[q+1], u1);
            u2 = fmaf(f_s[t][q+2], w[q+2], u2);
            u3 = fmaf(f_s[t][q+3], w[q+3], u3);
        }
        float u = (u0 + u1) + (u2 + u3);
        float eu = __expf(-fabsf(u));
        float opp = 1.f + eu;
        float d = fmaxf(u, 0.f) + __logf(opp);
        float dx = d * x_cur;
        if (fast) {
            float r = (u > 0.f ? eu : 1.f) * __fdividef(1.f, opp);
            Rp *= r;
            float p[16];
            pow_tree(r, p);
#pragma unroll
            for (int n = 0; n < NS; n++)
                h[n] = fmaf(p[n], h[n], dx * Bsm[t * NS + n]);
        } else {
#pragma unroll
            for (int n = 0; n < NS; n++) {
                float dA = __expf(d * A_[n]);
                Pn[n] *= dA;
                h[n] = fmaf(dA, h[n], dx * Bsm[t * NS + n]);
            }
        }
        x_cur = x_nxt;
    }
    if (fast) pow_tree(Rp, Pn);
    size_t base = (size_t)((s * BB + b) * NCHK + c) * 32 * EDI + e;
#pragma unroll
    for (int n = 0; n < NS; n++) g_sum[base + (size_t)n * EDI] = h[n];
#pragma unroll
    for (int n = 0; n < NS; n++) g_sum[base + (size_t)(16 + n) * EDI] = Pn[n];
}

// ---------- scan phase 2: chunk combine, all loads prefetched ---------------
__global__ __launch_bounds__(512)
void scan2() {
    int n = blockIdx.x & 15;
    int sb = blockIdx.x >> 4;
    int e = threadIdx.x;
    float hl[NCHK], Pv[NCHK];
#pragma unroll
    for (int c = 0; c < NCHK; c++) {
        size_t pb = (size_t)(sb * NCHK + c) * 32 * EDI + e;
        hl[c] = g_sum[pb + (size_t)n * EDI];
        Pv[c] = g_sum[pb + (size_t)(16 + n) * EDI];
    }
    float h = 0.f;
#pragma unroll
    for (int c = 0; c < NCHK; c++) {
        g_h0[(size_t)(sb * NCHK + c) * NS * EDI + (size_t)n * EDI + e] = h;
        h = fmaf(Pv[c], h, hl[c]);
    }
}

// -------- scan phase 3: full walk + gate, delta fused, channel-quarter ------
__global__ __launch_bounds__(128)
void scan3(AllPtrs P) {
    __shared__ float f_s[CLEN][NS];
    __shared__ float Bsm[CLEN * NS];
    __shared__ float Csm[CLEN * NS];
    int blk = blockIdx.x;
    int quarter = blk & 3;
    int blk2 = blk >> 2;
    int s = blk2 / (BB * NCHK);
    int rem = blk2 % (BB * NCHK);
    int b = rem / NCHK, c = rem % NCHK;
    int e0 = quarter * EQ;
    int e = e0 + threadIdx.x;
    for (int idx = threadIdx.x; idx < CLEN * DBCW; idx += blockDim.x) {
        int t = idx / DBCW, q = idx % DBCW;
        float v = g_dbc[s][(size_t)(b * LSEQ + c * CLEN + t) * DBCW + q];
        if (q < 16)      f_s[t][q] = v;
        else if (q < 32) Bsm[t * NS + (q - 16)] = v;
        else             Csm[t * NS + (q - 32)] = v;
    }
    const float* dtw = P.br[s].dtw + (size_t)e * RRW;
    float w[RRW];
    {
        float4 w0 = *(const float4*)dtw;
        float4 w1 = *(const float4*)(dtw + 4);
        float4 w2 = *(const float4*)(dtw + 8);
        float4 w3 = *(const float4*)(dtw + 12);
        w[0]=w0.x; w[1]=w0.y; w[2]=w0.z; w[3]=w0.w;
        w[4]=w1.x; w[5]=w1.y; w[6]=w1.z; w[7]=w1.w;
        w[8]=w2.x; w[9]=w2.y; w[10]=w2.z; w[11]=w2.w;
        w[12]=w3.x; w[13]=w3.y; w[14]=w3.z; w[15]=w3.w;
    }
    float dtb = P.br[s].dtb[e];
    int fast = g_fast[s];
    float A_[NS];
    if (!fast) {
        const float* Al = P.br[s].Al;
#pragma unroll
        for (int n = 0; n < NS; n++) A_[n] = -__expf(Al[e * NS + n]);
    }
    float Dv = P.br[s].Dp[e];
    float h[NS];
    {
        size_t sb = (size_t)((s * BB + b) * NCHK + c);
        size_t hb = sb * NS * EDI + e;
#pragma unroll
        for (int n = 0; n < NS; n++) h[n] = g_h0[hb + (size_t)n * EDI];
    }
    __syncthreads();
    int l0 = c * CLEN;
    size_t bbase = (size_t)(b * LSEQ);
    const float* xptr = g_xa[s] + (size_t)(bbase + l0) * EDI + e;
    float* gout = g_g[s] + (size_t)(bbase + l0) * EDI + e;
    float x_cur = *xptr;
    const float* xn = xptr + EDI;
    float za_cur = g_xz[(bbase + in_row(s, l0)) * ED2 + EDI + e];
    for (int t = 0; t < CLEN; t++) {
        float x_nxt = 0.f, za_nxt = 0.f;
        if (t + 1 < CLEN) {
            x_nxt = *xn;
            za_nxt = g_xz[(bbase + in_row(s, l0 + t + 1)) * ED2 + EDI + e];
        }
        xn += EDI;
        float u0 = dtb, u1 = 0.f, u2 = 0.f, u3 = 0.f;
#pragma unroll
        for (int q = 0; q < RRW; q += 4) {
            u0 = fmaf(f_s[t][q],   w[q],   u0);
            u1 = fmaf(f_s[t][q+1], w[q+1], u1);
            u2 = fmaf(f_s[t][q+2], w[q+2], u2);
            u3 = fmaf(f_s[t][q+3], w[q+3], u3);
        }
        float u = (u0 + u1) + (u2 + u3);
        float eu = __expf(-fabsf(u));
        float opp = 1.f + eu;
        float d = fmaxf(u, 0.f) + __logf(opp);
        float dx = d * x_cur;
        float acc = Dv * x_cur;
        if (fast) {
            float r = (u > 0.f ? eu : 1.f) * __fdividef(1.f, opp);
            float p[16];
            pow_tree(r, p);
#pragma unroll
            for (int n = 0; n < NS; n++) {
                h[n] = fmaf(p[n], h[n], dx * Bsm[t * NS + n]);
                acc = fmaf(h[n], Csm[t * NS + n], acc);
            }
        } else {
#pragma unroll
            for (int n = 0; n < NS; n++) {
                float dA = __expf(d * A_[n]);
                h[n] = fmaf(dA, h[n], dx * Bsm[t * NS + n]);
                acc = fmaf(h[n], Csm[t * NS + n], acc);
            }
        }
        float sz = za_cur * __fdividef(1.f, 1.f + __expf(-za_cur));
        *gout = acc * sz;
        gout += EDI;
        x_cur = x_nxt; za_cur = za_nxt;
    }
}

// ------------------------- launch ------------------------------------------
extern "C" void kernel_launch(void* const* d_in, const int* in_sizes, int n_in,
                              void* d_out, int out_size) {
    const float* x     = (const float*)d_in[0];
    const float* in_w  = (const float*)d_in[1];
    const float* out_w = (const float*)d_in[2];
    AllPtrs P;
    for (int s = 0; s < NBR; s++) {
        int o = 3 + 7 * s;
        P.br[s].cw  = (const float*)d_in[o + 0];
        P.br[s].cb  = (const float*)d_in[o + 1];
        P.br[s].xpw = (const float*)d_in[o + 2];
        P.br[s].dtw = (const float*)d_in[o + 3];
        P.br[s].dtb = (const float*)d_in[o + 4];
        P.br[s].Al  = (const float*)d_in[o + 5];
        P.br[s].Dp  = (const float*)d_in[o + 6];
    }
    float *p_xz, *p_dbc;
    cudaGetSymbolAddress((void**)&p_xz,  g_xz);
    cudaGetSymbolAddress((void**)&p_dbc, g_dbc);

    flag_kernel<<<NBR, EDI>>>(P);

    // xz = x @ in_w^T : bf16x3, 128x64 tiles, 272 blocks
    in_gemm_mma<<<dim3(ED2 / 64, (BLT + 127) / 128), 256>>>(x, in_w, p_xz);

    // per-branch permuted depthwise conv + SiLU — 1368 blocks
    conv_silu<<<NBR * BB * (LSEQ / CONV_T), 512>>>(P);

    // dBC = xa @ xp_w^T : bf16x3, split-K(4), 528 blocks
    cudaMemsetAsync(p_dbc, 0, (size_t)NBR * BLT * DBCW * sizeof(float));
    dbc_mma<<<dim3(NBR, (BLT + 63) / 64, 4), 256>>>(P);

    // chunked selective scan — 576 / 128 / 576 blocks (NCHK=18)
    scan1<<<NBR * BB * NCHK * 4, 128>>>(P);
    scan2<<<NBR * BB * NS, EDI>>>();
    scan3<<<NBR * BB * NCHK * 4, 128>>>(P);

    // combine permuted branch outputs into y — 2052 blocks, float4
    combine_k<<<BLT, 128>>>();

    // out = y @ out_w^T : bf16x3, split-K(2), 264 blocks
    cudaMemsetAsync(d_out, 0, (size_t)BLT * DMO * sizeof(float));
    out_gemm_mma<<<dim3(DMO / 64, (BLT + 63) / 64, 2), 256>>>(out_w, (float*)d_out);
}